// round 6
// baseline (speedup 1.0000x reference)
#include <cuda_runtime.h>
#include <cuda_bf16.h>
#include <stdint.h>

#define DINLINE __device__ __forceinline__

DINLINE uint32_t smem_u32(const void* p) {
    uint32_t a;
    asm("{ .reg .u64 t; cvta.to.shared.u64 t, %1; cvt.u32.u64 %0, t; }" : "=r"(a) : "l"(p));
    return a;
}

DINLINE void ldsm_x4(uint32_t addr, uint32_t* r) {
    asm volatile("ldmatrix.sync.aligned.m8n8.x4.shared.b16 {%0,%1,%2,%3}, [%4];"
                 : "=r"(r[0]), "=r"(r[1]), "=r"(r[2]), "=r"(r[3]) : "r"(addr));
}

DINLINE void mma16816(float* d, const uint32_t* a, const uint32_t* b) {
    asm volatile("mma.sync.aligned.m16n8k16.row.col.f32.bf16.bf16.f32 "
                 "{%0,%1,%2,%3}, {%4,%5,%6,%7}, {%8,%9}, {%0,%1,%2,%3};"
                 : "+f"(d[0]), "+f"(d[1]), "+f"(d[2]), "+f"(d[3])
                 : "r"(a[0]), "r"(a[1]), "r"(a[2]), "r"(a[3]), "r"(b[0]), "r"(b[1]));
}

DINLINE void cp16(uint32_t saddr, const void* g) {
    asm volatile("cp.async.cg.shared.global [%0], [%1], 16;" :: "r"(saddr), "l"(g));
}
DINLINE void cp_commit() { asm volatile("cp.async.commit_group;" ::: "memory"); }
DINLINE void cp_wait1() { asm volatile("cp.async.wait_group 1;" ::: "memory"); }
DINLINE void cp_wait0() { asm volatile("cp.async.wait_group 0;" ::: "memory"); }

DINLINE void split2(float a, float b, __nv_bfloat162& h, __nv_bfloat162& l) {
    h = __floats2bfloat162_rn(a, b);
    l = __floats2bfloat162_rn(a - __low2float(h), b - __high2float(h));
}

// ======================= scratch (no allocs) =======================
__device__ __align__(16) __nv_bfloat16 g_e128h[1024 * 128];
__device__ __align__(16) __nv_bfloat16 g_e128l[1024 * 128];
__device__ __align__(16) __nv_bfloat16 g_e256h[1024 * 256];
__device__ __align__(16) __nv_bfloat16 g_e256l[1024 * 256];
__device__ __align__(16) __nv_bfloat16 g_e512h[1024 * 512];
__device__ __align__(16) __nv_bfloat16 g_e512l[1024 * 512];
__device__ __align__(16) __nv_bfloat16 g_e1024h[1024 * 1024];
__device__ __align__(16) __nv_bfloat16 g_e1024l[1024 * 1024];
__device__ __align__(16) __nv_bfloat16 g_r1wh[256 * 128];
__device__ __align__(16) __nv_bfloat16 g_r1wl[256 * 128];
__device__ __align__(16) __nv_bfloat16 g_r2wh[512 * 256];
__device__ __align__(16) __nv_bfloat16 g_r2wl[512 * 256];
__device__ __align__(16) __nv_bfloat16 g_r3wh[1024 * 512];
__device__ __align__(16) __nv_bfloat16 g_r3wl[1024 * 512];
__device__ __align__(16) __nv_bfloat16 g_wabh[1024 * 1024];
__device__ __align__(16) __nv_bfloat16 g_wabl[1024 * 1024];
__device__ __align__(16) float g_r3p[2 * 1024 * 1024];   // r3 split-K partials
__device__ __align__(16) float g_AB[2 * 1024 * 1024];    // AB split-K partials
__device__ __align__(16) float g_m[16 * 512];

// ======================= fused prep: all weight splits + embedding =======================
DINLINE void split_store4(const float4* __restrict__ src, __nv_bfloat162* __restrict__ h,
                          __nv_bfloat162* __restrict__ l, int i) {
    float4 v = src[i];
    __nv_bfloat162 h0, l0, h1, l1;
    split2(v.x, v.y, h0, l0);
    split2(v.z, v.w, h1, l1);
    h[2 * i] = h0; h[2 * i + 1] = h1;
    l[2 * i] = l0; l[2 * i + 1] = l1;
}

// blocks: [0,32) r1w, [32,160) r2w, [160,672) r3w, [672,1696) w1 gather, [1696,2208) embed
__global__ __launch_bounds__(256) void prep_kernel(
    const float* __restrict__ r1w, __nv_bfloat162* __restrict__ r1h, __nv_bfloat162* __restrict__ r1l,
    const float* __restrict__ r2w, __nv_bfloat162* __restrict__ r2h, __nv_bfloat162* __restrict__ r2l,
    const float* __restrict__ r3w, __nv_bfloat162* __restrict__ r3h, __nv_bfloat162* __restrict__ r3l,
    const float* __restrict__ w1, __nv_bfloat162* __restrict__ wabh, __nv_bfloat162* __restrict__ wabl,
    const float* __restrict__ x,
    const float* __restrict__ e1w, const float* __restrict__ e1b,
    const float* __restrict__ e2w, const float* __restrict__ e2b,
    __nv_bfloat16* __restrict__ oh, __nv_bfloat16* __restrict__ ol) {
    int b = blockIdx.x, tid = threadIdx.x;
    if (b < 32) {
        split_store4((const float4*)r1w, r1h, r1l, b * 256 + tid);
    } else if (b < 160) {
        split_store4((const float4*)r2w, r2h, r2l, (b - 32) * 256 + tid);
    } else if (b < 672) {
        split_store4((const float4*)r3w, r3h, r3l, (b - 160) * 256 + tid);
    } else if (b < 1696) {
        int i = (b - 672) * 256 + tid;      // over 1024*256 float4 groups
        int n = i >> 8, kq = i & 255;
        const float* src = (n < 512) ? (w1 + (size_t)n * 2048 + kq * 4)
                                     : (w1 + (size_t)(n - 512) * 2048 + 1024 + kq * 4);
        float4 v = *(const float4*)src;
        __nv_bfloat162 h0, l0, h1, l1;
        split2(v.x, v.y, h0, l0);
        split2(v.z, v.w, h1, l1);
        size_t o = (size_t)n * 512 + kq * 2;
        wabh[o] = h0; wabh[o + 1] = h1;
        wabl[o] = l0; wabl[o + 1] = l1;
    } else {
        __shared__ float xr[2][16];
        int rb = tid >> 7;
        int t = tid & 127;
        int row = (b - 1696) * 2 + rb;
        if (t < 16) xr[rb][t] = x[row * 16 + t];
        __syncthreads();
        float s1 = e1b[t];
#pragma unroll
        for (int c = 0; c < 3; c++) s1 = fmaf(xr[rb][c], e1w[t * 3 + c], s1);
        float s2 = e2b[t];
#pragma unroll
        for (int c = 0; c < 13; c++) s2 = fmaf(xr[rb][3 + c], e2w[t * 13 + c], s2);
        float v = fmaxf(s1, 0.f) + fmaxf(s2, 0.f);
        __nv_bfloat16 h = __float2bfloat16(v);
        oh[row * 128 + t] = h;
        ol[row * 128 + t] = __float2bfloat16(v - __bfloat162float(h));
    }
}

// ======================= warp-mma split-bf16 GEMM, 2-stage cp.async, split-K =======================
// C[m][n] = sum_k (Ah+Al)[m][k] * (Wh+Wl)[n][k], 3-term split, fp32 accumulate.
// CTA tile BM x 64, BM*2 threads, warp tile 32x32. Reduction length K (mult of 64),
// row stride ldk. blockIdx.z selects K-slice (koff = z*K) and partial buffer (z*pstride).
// OUTM==0: raw fp32 out. OUTM==1: bias+relu, split bf16 out (gridDim.z must be 1).
static constexpr int GSTRIDE = 144;   // 64 bf16 = 128B + 16B pad

template <int BM> struct GemmCfg {
    static constexpr int T = BM * 2;
    static constexpr int OFF_AL = BM * GSTRIDE;
    static constexpr int OFF_WH = 2 * BM * GSTRIDE;
    static constexpr int OFF_WL = OFF_WH + 64 * GSTRIDE;
    static constexpr int STAGE = OFF_WL + 64 * GSTRIDE;
    static constexpr int SMEM = 2 * STAGE;
};

template <int BM, int OUTM>
__global__ __launch_bounds__(BM * 2) void mma_gemm(
    const __nv_bfloat16* __restrict__ Ah, const __nv_bfloat16* __restrict__ Al,
    const __nv_bfloat16* __restrict__ Wh, const __nv_bfloat16* __restrict__ Wl,
    const float* __restrict__ bias, int K, int ldk, size_t pstride,
    float* __restrict__ outF, __nv_bfloat16* __restrict__ outH,
    __nv_bfloat16* __restrict__ outL, int ldo) {
    using C = GemmCfg<BM>;
    extern __shared__ char smc[];
    uint32_t sbase = smem_u32(smc);

    int tid = threadIdx.x, lane = tid & 31, wid = tid >> 5;
    int mw = wid >> 1, nw = wid & 1;
    int m0 = blockIdx.y * BM, n0 = blockIdx.x * 64;

    size_t koff = (size_t)blockIdx.z * K;
    Ah += koff; Al += koff; Wh += koff; Wl += koff;
    if (OUTM == 0) outF += (size_t)blockIdx.z * pstride;

    float acc[2][4][4] = {};

    uint32_t aoff = (lane & 15) * GSTRIDE + ((lane >> 4) << 4);
    uint32_t boff = ((((lane >> 4) << 3) + (lane & 7)) * GSTRIDE) + (((lane >> 3) & 1) << 4);
    uint32_t aBase0 = sbase + mw * 32 * GSTRIDE + aoff;
    uint32_t bBase0 = sbase + C::OFF_WH + nw * 32 * GSTRIDE + boff;

    constexpr int RPI = C::T / 8;
    int lrow = tid >> 3, lu = tid & 7;
    uint32_t sAh = sbase, sAl = sbase + C::OFF_AL, sWh = sbase + C::OFF_WH, sWl = sbase + C::OFF_WL;

    int nc = K >> 6;

    auto load_stage = [&](int c) {
        int s = c & 1;
        int k0 = c << 6;
        uint32_t so = s * C::STAGE;
#pragma unroll
        for (int q = 0; q < BM / RPI; ++q) {
            int row = lrow + q * RPI;
            size_t go = (size_t)(m0 + row) * ldk + k0 + lu * 8;
            uint32_t sro = row * GSTRIDE + lu * 16 + so;
            cp16(sAh + sro, Ah + go);
            cp16(sAl + sro, Al + go);
        }
#pragma unroll
        for (int q = 0; q < 64 / RPI; ++q) {
            int row = lrow + q * RPI;
            size_t go = (size_t)(n0 + row) * ldk + k0 + lu * 8;
            uint32_t sro = row * GSTRIDE + lu * 16 + so;
            cp16(sWh + sro, Wh + go);
            cp16(sWl + sro, Wl + go);
        }
        cp_commit();
    };

    load_stage(0);
    for (int c = 0; c < nc; ++c) {
        if (c + 1 < nc) { load_stage(c + 1); cp_wait1(); } else { cp_wait0(); }
        __syncthreads();
        uint32_t so = (c & 1) * C::STAGE;
        uint32_t aBase = aBase0 + so, bBase = bBase0 + so;
#pragma unroll
        for (int kk = 0; kk < 4; ++kk) {
            uint32_t ah[2][4], al[2][4], bh[4][2], bl[4][2];
#pragma unroll
            for (int mi = 0; mi < 2; ++mi) {
                ldsm_x4(aBase + mi * (16 * GSTRIDE) + kk * 32, ah[mi]);
                ldsm_x4(aBase + C::OFF_AL + mi * (16 * GSTRIDE) + kk * 32, al[mi]);
            }
#pragma unroll
            for (int p = 0; p < 2; ++p) {
                uint32_t r4[4];
                ldsm_x4(bBase + p * (16 * GSTRIDE) + kk * 32, r4);
                bh[2 * p][0] = r4[0]; bh[2 * p][1] = r4[1];
                bh[2 * p + 1][0] = r4[2]; bh[2 * p + 1][1] = r4[3];
                ldsm_x4(bBase + (C::OFF_WL - C::OFF_WH) + p * (16 * GSTRIDE) + kk * 32, r4);
                bl[2 * p][0] = r4[0]; bl[2 * p][1] = r4[1];
                bl[2 * p + 1][0] = r4[2]; bl[2 * p + 1][1] = r4[3];
            }
#pragma unroll
            for (int mi = 0; mi < 2; ++mi)
#pragma unroll
                for (int ni = 0; ni < 4; ++ni) {
                    mma16816(acc[mi][ni], ah[mi], bh[ni]);
                    mma16816(acc[mi][ni], ah[mi], bl[ni]);
                    mma16816(acc[mi][ni], al[mi], bh[ni]);
                }
        }
        __syncthreads();
    }

    int r = lane >> 2, c2 = (lane & 3) * 2;
    int warpM = m0 + mw * 32, warpN = n0 + nw * 32;
#pragma unroll
    for (int mi = 0; mi < 2; ++mi)
#pragma unroll
        for (int ni = 0; ni < 4; ++ni) {
            int n = warpN + ni * 8 + c2;
#pragma unroll
            for (int h = 0; h < 2; ++h) {
                int m = warpM + mi * 16 + r + h * 8;
                float v0 = acc[mi][ni][h * 2 + 0];
                float v1 = acc[mi][ni][h * 2 + 1];
                if (OUTM == 1) {
                    float2 bb = *(const float2*)(bias + n);
                    v0 = fmaxf(v0 + bb.x, 0.f);
                    v1 = fmaxf(v1 + bb.y, 0.f);
                    __nv_bfloat162 hh, ll;
                    split2(v0, v1, hh, ll);
                    *(__nv_bfloat162*)(outH + (size_t)m * ldo + n) = hh;
                    *(__nv_bfloat162*)(outL + (size_t)m * ldo + n) = ll;
                } else {
                    *(float2*)(outF + (size_t)m * ldo + n) = make_float2(v0, v1);
                }
            }
        }
}

// ======================= r3 split-K combine: relu(p0+p1+bias) -> split bf16 =======================
__global__ __launch_bounds__(256) void combine_r3(const float* __restrict__ p0,
                                                  const float* __restrict__ p1,
                                                  const float* __restrict__ bias,
                                                  __nv_bfloat16* __restrict__ oh,
                                                  __nv_bfloat16* __restrict__ ol) {
    int i = blockIdx.x * 256 + threadIdx.x;   // over 1024*1024/4 float4 groups
    int n4 = (i & 255) * 4;                   // column of first element
    float4 a = *(const float4*)(p0 + (size_t)i * 4);
    float4 b = *(const float4*)(p1 + (size_t)i * 4);
    float4 bb = *(const float4*)(bias + n4);
    float v0 = fmaxf(a.x + b.x + bb.x, 0.f);
    float v1 = fmaxf(a.y + b.y + bb.y, 0.f);
    float v2 = fmaxf(a.z + b.z + bb.z, 0.f);
    float v3 = fmaxf(a.w + b.w + bb.w, 0.f);
    __nv_bfloat162 h0, l0, h1, l1;
    split2(v0, v1, h0, l0);
    split2(v2, v3, h1, l1);
    *(__nv_bfloat162*)(oh + (size_t)i * 4) = h0;
    *(__nv_bfloat162*)(oh + (size_t)i * 4 + 2) = h1;
    *(__nv_bfloat162*)(ol + (size_t)i * 4) = l0;
    *(__nv_bfloat162*)(ol + (size_t)i * 4 + 2) = l1;
}

// ======================= pairwise relu outer-sum mean (sums AB partials) =======================
__global__ __launch_bounds__(256) void pairwise_kernel(const float* __restrict__ AB,
                                                       const float* __restrict__ b1,
                                                       float* __restrict__ mout) {
    __shared__ float As[64][64];
    __shared__ float Bs[64][64];
    __shared__ float part[4][64];
    int t = threadIdx.x;
    int chunk = blockIdx.x;
    int b = blockIdx.y;
    int c0 = chunk * 64;
    const float* base0 = AB + (size_t)b * 64 * 1024;
    const float* base1 = base0 + 1024 * 1024;

#pragma unroll
    for (int q = 0; q < 4; q++) {
        int idx = t + q * 256;
        int row = idx >> 4;
        int seg = idx & 15;
        size_t oa = (size_t)row * 1024 + c0 + seg * 4;
        size_t ob = (size_t)row * 1024 + 512 + c0 + seg * 4;
        float4 a0 = *(const float4*)(base0 + oa);
        float4 a1 = *(const float4*)(base1 + oa);
        float4 b0 = *(const float4*)(base0 + ob);
        float4 b1v = *(const float4*)(base1 + ob);
        As[row][seg * 4 + 0] = a0.x + a1.x;
        As[row][seg * 4 + 1] = a0.y + a1.y;
        As[row][seg * 4 + 2] = a0.z + a1.z;
        As[row][seg * 4 + 3] = a0.w + a1.w;
        Bs[row][seg * 4 + 0] = b0.x + b1v.x;
        Bs[row][seg * 4 + 1] = b0.y + b1v.y;
        Bs[row][seg * 4 + 2] = b0.z + b1v.z;
        Bs[row][seg * 4 + 3] = b0.w + b1v.w;
    }
    __syncthreads();

    int c = t & 63;
    int ig = t >> 6;
    float bias = b1[c0 + c];
    float acc = 0.f;
    for (int i = ig * 16; i < ig * 16 + 16; i++) {
        float bb = Bs[i][c] + bias;
#pragma unroll
        for (int j = 0; j < 64; j++)
            acc += fmaxf(As[j][c] + bb, 0.f);
    }
    part[ig][c] = acc;
    __syncthreads();
    if (t < 64) {
        float s = part[0][t] + part[1][t] + part[2][t] + part[3][t];
        mout[b * 512 + c0 + t] = s * (1.0f / 4096.0f);
    }
}

// ======================= final 512 -> 2048 =======================
__global__ __launch_bounds__(256) void final_kernel(const float* __restrict__ m,
                                                    const float* __restrict__ w2,
                                                    const float* __restrict__ b2,
                                                    float* __restrict__ out) {
    __shared__ float sm[16 * 512];
    int t = threadIdx.x;
    for (int i = t; i < 16 * 512; i += 256) sm[i] = m[i];
    __syncthreads();

    int warp = t >> 5, lane = t & 31;
    int o = blockIdx.x * 8 + warp;
    float acc[16];
#pragma unroll
    for (int b = 0; b < 16; b++) acc[b] = 0.f;
    const float* wrow = w2 + (size_t)o * 512;
#pragma unroll
    for (int kc = 0; kc < 16; kc++) {
        int k = kc * 32 + lane;
        float wv = wrow[k];
#pragma unroll
        for (int b = 0; b < 16; b++) acc[b] = fmaf(wv, sm[b * 512 + k], acc[b]);
    }
#pragma unroll
    for (int b = 0; b < 16; b++) {
        float v = acc[b];
#pragma unroll
        for (int s = 16; s > 0; s >>= 1) v += __shfl_xor_sync(0xffffffffu, v, s);
        if (lane == 0) out[b * 2048 + o] = v + b2[o];
    }
}

// ======================= launch =======================
extern "C" void kernel_launch(void* const* d_in, const int* in_sizes, int n_in,
                              void* d_out, int out_size) {
    (void)in_sizes; (void)n_in; (void)out_size;
    const float* x   = (const float*)d_in[0];
    const float* e1w = (const float*)d_in[1];
    const float* e1b = (const float*)d_in[2];
    const float* e2w = (const float*)d_in[3];
    const float* e2b = (const float*)d_in[4];
    const float* r1w = (const float*)d_in[5];
    const float* r1b = (const float*)d_in[6];
    const float* r2w = (const float*)d_in[7];
    const float* r2b = (const float*)d_in[8];
    const float* r3w = (const float*)d_in[9];
    const float* r3b = (const float*)d_in[10];
    const float* w1  = (const float*)d_in[11];
    const float* b1  = (const float*)d_in[12];
    const float* w2  = (const float*)d_in[13];
    const float* b2  = (const float*)d_in[14];
    float* out = (float*)d_out;

    __nv_bfloat16 *e128h, *e128l, *e256h, *e256l, *e512h, *e512l, *e1024h, *e1024l;
    __nv_bfloat16 *r1wh, *r1wl, *r2wh, *r2wl, *r3wh, *r3wl, *wabh, *wabl;
    float *r3p, *AB, *mbuf;
    cudaGetSymbolAddress((void**)&e128h, g_e128h);
    cudaGetSymbolAddress((void**)&e128l, g_e128l);
    cudaGetSymbolAddress((void**)&e256h, g_e256h);
    cudaGetSymbolAddress((void**)&e256l, g_e256l);
    cudaGetSymbolAddress((void**)&e512h, g_e512h);
    cudaGetSymbolAddress((void**)&e512l, g_e512l);
    cudaGetSymbolAddress((void**)&e1024h, g_e1024h);
    cudaGetSymbolAddress((void**)&e1024l, g_e1024l);
    cudaGetSymbolAddress((void**)&r1wh, g_r1wh);
    cudaGetSymbolAddress((void**)&r1wl, g_r1wl);
    cudaGetSymbolAddress((void**)&r2wh, g_r2wh);
    cudaGetSymbolAddress((void**)&r2wl, g_r2wl);
    cudaGetSymbolAddress((void**)&r3wh, g_r3wh);
    cudaGetSymbolAddress((void**)&r3wl, g_r3wl);
    cudaGetSymbolAddress((void**)&wabh, g_wabh);
    cudaGetSymbolAddress((void**)&wabl, g_wabl);
    cudaGetSymbolAddress((void**)&r3p, g_r3p);
    cudaGetSymbolAddress((void**)&AB, g_AB);
    cudaGetSymbolAddress((void**)&mbuf, g_m);

    cudaFuncSetAttribute(mma_gemm<64, 1>, cudaFuncAttributeMaxDynamicSharedMemorySize, GemmCfg<64>::SMEM);
    cudaFuncSetAttribute(mma_gemm<128, 0>, cudaFuncAttributeMaxDynamicSharedMemorySize, GemmCfg<128>::SMEM);

    // fused prep: all weight splits + embedding
    prep_kernel<<<2208, 256>>>(r1w, (__nv_bfloat162*)r1wh, (__nv_bfloat162*)r1wl,
                               r2w, (__nv_bfloat162*)r2wh, (__nv_bfloat162*)r2wl,
                               r3w, (__nv_bfloat162*)r3wh, (__nv_bfloat162*)r3wl,
                               w1, (__nv_bfloat162*)wabh, (__nv_bfloat162*)wabl,
                               x, e1w, e1b, e2w, e2b, e128h, e128l);

    // r1: 128 -> 256 (bias+relu, split out), BM=64
    mma_gemm<64, 1><<<dim3(4, 16, 1), 128, GemmCfg<64>::SMEM>>>(
        e128h, e128l, r1wh, r1wl, r1b, 128, 128, 0, nullptr, e256h, e256l, 256);
    // r2: 256 -> 512, BM=64
    mma_gemm<64, 1><<<dim3(8, 16, 1), 128, GemmCfg<64>::SMEM>>>(
        e256h, e256l, r2wh, r2wl, r2b, 256, 256, 0, nullptr, e512h, e512l, 512);
    // r3: 512 -> 1024, split-K x2 -> fp32 partials
    mma_gemm<128, 0><<<dim3(16, 8, 2), 256, GemmCfg<128>::SMEM>>>(
        e512h, e512l, r3wh, r3wl, nullptr, 256, 512, (size_t)1024 * 1024,
        r3p, nullptr, nullptr, 1024);
    // combine r3 partials -> bias+relu -> split bf16
    combine_r3<<<1024, 256>>>(r3p, r3p + 1024 * 1024, r3b, e1024h, e1024l);
    // A|B fused: 1024 -> 1024, split-K x2 -> fp32 partials
    mma_gemm<128, 0><<<dim3(16, 8, 2), 256, GemmCfg<128>::SMEM>>>(
        e1024h, e1024l, wabh, wabl, nullptr, 512, 1024, (size_t)1024 * 1024,
        AB, nullptr, nullptr, 1024);

    // pairwise mean (sums AB partials) -> m[16][512]
    pairwise_kernel<<<dim3(8, 16), 256>>>(AB, b1, mbuf);

    // final 512 -> 2048
    final_kernel<<<2048 / 8, 256>>>(mbuf, w2, b2, out);
}

// round 7
// speedup vs baseline: 1.3889x; 1.3889x over previous
#include <cuda_runtime.h>
#include <cuda_bf16.h>
#include <stdint.h>

#define DINLINE __device__ __forceinline__

DINLINE uint32_t smem_u32(const void* p) {
    uint32_t a;
    asm("{ .reg .u64 t; cvta.to.shared.u64 t, %1; cvt.u32.u64 %0, t; }" : "=r"(a) : "l"(p));
    return a;
}

DINLINE void ldsm_x4(uint32_t addr, uint32_t* r) {
    asm volatile("ldmatrix.sync.aligned.m8n8.x4.shared.b16 {%0,%1,%2,%3}, [%4];"
                 : "=r"(r[0]), "=r"(r[1]), "=r"(r[2]), "=r"(r[3]) : "r"(addr));
}

DINLINE void mma16816(float* d, const uint32_t* a, const uint32_t* b) {
    asm volatile("mma.sync.aligned.m16n8k16.row.col.f32.bf16.bf16.f32 "
                 "{%0,%1,%2,%3}, {%4,%5,%6,%7}, {%8,%9}, {%0,%1,%2,%3};"
                 : "+f"(d[0]), "+f"(d[1]), "+f"(d[2]), "+f"(d[3])
                 : "r"(a[0]), "r"(a[1]), "r"(a[2]), "r"(a[3]), "r"(b[0]), "r"(b[1]));
}

DINLINE void cp16(uint32_t saddr, const void* g) {
    asm volatile("cp.async.cg.shared.global [%0], [%1], 16;" :: "r"(saddr), "l"(g));
}
DINLINE void cp_commit() { asm volatile("cp.async.commit_group;" ::: "memory"); }
DINLINE void cp_wait1() { asm volatile("cp.async.wait_group 1;" ::: "memory"); }
DINLINE void cp_wait0() { asm volatile("cp.async.wait_group 0;" ::: "memory"); }

DINLINE void split2(float a, float b, __nv_bfloat162& h, __nv_bfloat162& l) {
    h = __floats2bfloat162_rn(a, b);
    l = __floats2bfloat162_rn(a - __low2float(h), b - __high2float(h));
}

// ======================= scratch (no allocs) =======================
__device__ __align__(16) __nv_bfloat16 g_e128h[1024 * 128];
__device__ __align__(16) __nv_bfloat16 g_e128l[1024 * 128];
__device__ __align__(16) __nv_bfloat16 g_e256h[1024 * 256];
__device__ __align__(16) __nv_bfloat16 g_e256l[1024 * 256];
__device__ __align__(16) __nv_bfloat16 g_e512h[1024 * 512];
__device__ __align__(16) __nv_bfloat16 g_e512l[1024 * 512];
__device__ __align__(16) __nv_bfloat16 g_e1024h[1024 * 1024];
__device__ __align__(16) __nv_bfloat16 g_e1024l[1024 * 1024];
__device__ __align__(16) __nv_bfloat16 g_r1wh[256 * 128];
__device__ __align__(16) __nv_bfloat16 g_r1wl[256 * 128];
__device__ __align__(16) __nv_bfloat16 g_r2wh[512 * 256];
__device__ __align__(16) __nv_bfloat16 g_r2wl[512 * 256];
__device__ __align__(16) __nv_bfloat16 g_r3wh[1024 * 512];
__device__ __align__(16) __nv_bfloat16 g_r3wl[1024 * 512];
__device__ __align__(16) __nv_bfloat16 g_wabh[1024 * 1024];
__device__ __align__(16) __nv_bfloat16 g_wabl[1024 * 1024];
__device__ __align__(16) float g_AB[1024 * 1024];   // cols [0,512)=A, [512,1024)=B
__device__ __align__(16) float g_m[16 * 512];

// ======================= fused prep: all weight splits + embedding =======================
DINLINE void split_store4(const float4* __restrict__ src, __nv_bfloat162* __restrict__ h,
                          __nv_bfloat162* __restrict__ l, int i) {
    float4 v = src[i];
    __nv_bfloat162 h0, l0, h1, l1;
    split2(v.x, v.y, h0, l0);
    split2(v.z, v.w, h1, l1);
    h[2 * i] = h0; h[2 * i + 1] = h1;
    l[2 * i] = l0; l[2 * i + 1] = l1;
}

// blocks: [0,32) r1w, [32,160) r2w, [160,672) r3w, [672,1696) w1 gather, [1696,2208) embed
__global__ __launch_bounds__(256) void prep_kernel(
    const float* __restrict__ r1w, __nv_bfloat162* __restrict__ r1h, __nv_bfloat162* __restrict__ r1l,
    const float* __restrict__ r2w, __nv_bfloat162* __restrict__ r2h, __nv_bfloat162* __restrict__ r2l,
    const float* __restrict__ r3w, __nv_bfloat162* __restrict__ r3h, __nv_bfloat162* __restrict__ r3l,
    const float* __restrict__ w1, __nv_bfloat162* __restrict__ wabh, __nv_bfloat162* __restrict__ wabl,
    const float* __restrict__ x,
    const float* __restrict__ e1w, const float* __restrict__ e1b,
    const float* __restrict__ e2w, const float* __restrict__ e2b,
    __nv_bfloat16* __restrict__ oh, __nv_bfloat16* __restrict__ ol) {
    int b = blockIdx.x, tid = threadIdx.x;
    if (b < 32) {
        split_store4((const float4*)r1w, r1h, r1l, b * 256 + tid);
    } else if (b < 160) {
        split_store4((const float4*)r2w, r2h, r2l, (b - 32) * 256 + tid);
    } else if (b < 672) {
        split_store4((const float4*)r3w, r3h, r3l, (b - 160) * 256 + tid);
    } else if (b < 1696) {
        int i = (b - 672) * 256 + tid;      // over 1024*256 float4 groups
        int n = i >> 8, kq = i & 255;
        const float* src = (n < 512) ? (w1 + (size_t)n * 2048 + kq * 4)
                                     : (w1 + (size_t)(n - 512) * 2048 + 1024 + kq * 4);
        float4 v = *(const float4*)src;
        __nv_bfloat162 h0, l0, h1, l1;
        split2(v.x, v.y, h0, l0);
        split2(v.z, v.w, h1, l1);
        size_t o = (size_t)n * 512 + kq * 2;
        wabh[o] = h0; wabh[o + 1] = h1;
        wabl[o] = l0; wabl[o + 1] = l1;
    } else {
        __shared__ float xr[2][16];
        int rb = tid >> 7;
        int t = tid & 127;
        int row = (b - 1696) * 2 + rb;
        if (t < 16) xr[rb][t] = x[row * 16 + t];
        __syncthreads();
        float s1 = e1b[t];
#pragma unroll
        for (int c = 0; c < 3; c++) s1 = fmaf(xr[rb][c], e1w[t * 3 + c], s1);
        float s2 = e2b[t];
#pragma unroll
        for (int c = 0; c < 13; c++) s2 = fmaf(xr[rb][3 + c], e2w[t * 13 + c], s2);
        float v = fmaxf(s1, 0.f) + fmaxf(s2, 0.f);
        __nv_bfloat16 h = __float2bfloat16(v);
        oh[row * 128 + t] = h;
        ol[row * 128 + t] = __float2bfloat16(v - __bfloat162float(h));
    }
}

// ======================= warp-mma split-bf16 GEMM, 2-stage cp.async + frag prefetch =======================
// C[m][n] = sum_k (Ah+Al)[m][k] * (Wh+Wl)[n][k], 3-term split, fp32 accumulate.
// CTA tile BM x 64, BM*2 threads (BM/32 x 2 warps), warp tile 32x32. K mult of 64.
// OUTM==0: raw fp32 out. OUTM==1: bias+relu, split bf16 out.
static constexpr int GSTRIDE = 144;   // 64 bf16 = 128B + 16B pad

template <int BM> struct GemmCfg {
    static constexpr int T = BM * 2;
    static constexpr int OFF_AL = BM * GSTRIDE;
    static constexpr int OFF_WH = 2 * BM * GSTRIDE;
    static constexpr int OFF_WL = OFF_WH + 64 * GSTRIDE;
    static constexpr int STAGE = OFF_WL + 64 * GSTRIDE;
    static constexpr int SMEM = 2 * STAGE;
    static constexpr int MINB = (BM == 64) ? 2 : 1;
};

template <int BM, int OUTM>
__global__ __launch_bounds__(BM * 2, GemmCfg<BM>::MINB) void mma_gemm(
    const __nv_bfloat16* __restrict__ Ah, const __nv_bfloat16* __restrict__ Al,
    const __nv_bfloat16* __restrict__ Wh, const __nv_bfloat16* __restrict__ Wl,
    const float* __restrict__ bias, int K,
    float* __restrict__ outF, __nv_bfloat16* __restrict__ outH,
    __nv_bfloat16* __restrict__ outL, int ldo) {
    using C = GemmCfg<BM>;
    extern __shared__ char smc[];
    uint32_t sbase = smem_u32(smc);

    int tid = threadIdx.x, lane = tid & 31, wid = tid >> 5;
    int mw = wid >> 1, nw = wid & 1;
    int m0 = blockIdx.y * BM, n0 = blockIdx.x * 64;

    float acc[2][4][4] = {};

    uint32_t aoff = (lane & 15) * GSTRIDE + ((lane >> 4) << 4);
    uint32_t boff = ((((lane >> 4) << 3) + (lane & 7)) * GSTRIDE) + (((lane >> 3) & 1) << 4);
    uint32_t aBase0 = sbase + mw * 32 * GSTRIDE + aoff;
    uint32_t bBase0 = sbase + C::OFF_WH + nw * 32 * GSTRIDE + boff;

    constexpr int RPI = C::T / 8;
    int lrow = tid >> 3, lu = tid & 7;
    uint32_t sAh = sbase, sAl = sbase + C::OFF_AL, sWh = sbase + C::OFF_WH, sWl = sbase + C::OFF_WL;

    int nc = K >> 6;

    auto load_stage = [&](int c) {
        int s = c & 1;
        int k0 = c << 6;
        uint32_t so = s * C::STAGE;
#pragma unroll
        for (int q = 0; q < BM / RPI; ++q) {
            int row = lrow + q * RPI;
            size_t go = (size_t)(m0 + row) * K + k0 + lu * 8;
            uint32_t sro = row * GSTRIDE + lu * 16 + so;
            cp16(sAh + sro, Ah + go);
            cp16(sAl + sro, Al + go);
        }
#pragma unroll
        for (int q = 0; q < 64 / RPI; ++q) {
            int row = lrow + q * RPI;
            size_t go = (size_t)(n0 + row) * K + k0 + lu * 8;
            uint32_t sro = row * GSTRIDE + lu * 16 + so;
            cp16(sWh + sro, Wh + go);
            cp16(sWl + sro, Wl + go);
        }
        cp_commit();
    };

    // double-buffered register fragments (prefetch kk+1 during compute of kk)
    uint32_t ah[2][2][4], al[2][2][4], bh[2][4][2], bl[2][4][2];

#define LOAD_FRAGS(buf, aB, bB, kk)                                                     \
    do {                                                                                \
        _Pragma("unroll")                                                               \
        for (int mi = 0; mi < 2; ++mi) {                                                \
            ldsm_x4((aB) + mi * (16 * GSTRIDE) + (kk) * 32, ah[buf][mi]);               \
            ldsm_x4((aB) + C::OFF_AL + mi * (16 * GSTRIDE) + (kk) * 32, al[buf][mi]);   \
        }                                                                               \
        _Pragma("unroll")                                                               \
        for (int p = 0; p < 2; ++p) {                                                   \
            uint32_t r4[4];                                                             \
            ldsm_x4((bB) + p * (16 * GSTRIDE) + (kk) * 32, r4);                         \
            bh[buf][2 * p][0] = r4[0]; bh[buf][2 * p][1] = r4[1];                       \
            bh[buf][2 * p + 1][0] = r4[2]; bh[buf][2 * p + 1][1] = r4[3];               \
            ldsm_x4((bB) + (C::OFF_WL - C::OFF_WH) + p * (16 * GSTRIDE) + (kk) * 32, r4); \
            bl[buf][2 * p][0] = r4[0]; bl[buf][2 * p][1] = r4[1];                       \
            bl[buf][2 * p + 1][0] = r4[2]; bl[buf][2 * p + 1][1] = r4[3];               \
        }                                                                               \
    } while (0)

    load_stage(0);
    for (int c = 0; c < nc; ++c) {
        if (c + 1 < nc) { load_stage(c + 1); cp_wait1(); } else { cp_wait0(); }
        __syncthreads();
        uint32_t so = (c & 1) * C::STAGE;
        uint32_t aBase = aBase0 + so, bBase = bBase0 + so;
        LOAD_FRAGS(0, aBase, bBase, 0);
#pragma unroll
        for (int kk = 0; kk < 4; ++kk) {
            int cur = kk & 1, nxt = cur ^ 1;
            if (kk < 3) LOAD_FRAGS(nxt, aBase, bBase, kk + 1);
#pragma unroll
            for (int mi = 0; mi < 2; ++mi)
#pragma unroll
                for (int ni = 0; ni < 4; ++ni) {
                    mma16816(acc[mi][ni], ah[cur][mi], bh[cur][ni]);
                    mma16816(acc[mi][ni], ah[cur][mi], bl[cur][ni]);
                    mma16816(acc[mi][ni], al[cur][mi], bh[cur][ni]);
                }
        }
        __syncthreads();
    }
#undef LOAD_FRAGS

    int r = lane >> 2, c2 = (lane & 3) * 2;
    int warpM = m0 + mw * 32, warpN = n0 + nw * 32;
#pragma unroll
    for (int mi = 0; mi < 2; ++mi)
#pragma unroll
        for (int ni = 0; ni < 4; ++ni) {
            int n = warpN + ni * 8 + c2;
#pragma unroll
            for (int h = 0; h < 2; ++h) {
                int m = warpM + mi * 16 + r + h * 8;
                float v0 = acc[mi][ni][h * 2 + 0];
                float v1 = acc[mi][ni][h * 2 + 1];
                if (OUTM == 1) {
                    float2 bb = *(const float2*)(bias + n);
                    v0 = fmaxf(v0 + bb.x, 0.f);
                    v1 = fmaxf(v1 + bb.y, 0.f);
                    __nv_bfloat162 hh, ll;
                    split2(v0, v1, hh, ll);
                    *(__nv_bfloat162*)(outH + (size_t)m * ldo + n) = hh;
                    *(__nv_bfloat162*)(outL + (size_t)m * ldo + n) = ll;
                } else {
                    *(float2*)(outF + (size_t)m * ldo + n) = make_float2(v0, v1);
                }
            }
        }
}

// ======================= pairwise relu outer-sum mean =======================
__global__ __launch_bounds__(256) void pairwise_kernel(const float* __restrict__ AB,
                                                       const float* __restrict__ b1,
                                                       float* __restrict__ mout) {
    __shared__ float As[64][64];
    __shared__ float Bs[64][64];
    __shared__ float part[4][64];
    int t = threadIdx.x;
    int chunk = blockIdx.x;
    int b = blockIdx.y;
    int c0 = chunk * 64;
    const float* base = AB + (size_t)b * 64 * 1024;

#pragma unroll
    for (int q = 0; q < 4; q++) {
        int idx = t + q * 256;
        int row = idx >> 4;
        int seg = idx & 15;
        float4 va = *(const float4*)(base + row * 1024 + c0 + seg * 4);
        float4 vb = *(const float4*)(base + row * 1024 + 512 + c0 + seg * 4);
        *(float4*)&As[row][seg * 4] = va;
        *(float4*)&Bs[row][seg * 4] = vb;
    }
    __syncthreads();

    int c = t & 63;
    int ig = t >> 6;
    float bias = b1[c0 + c];
    float acc = 0.f;
    for (int i = ig * 16; i < ig * 16 + 16; i++) {
        float bb = Bs[i][c] + bias;
#pragma unroll
        for (int j = 0; j < 64; j++)
            acc += fmaxf(As[j][c] + bb, 0.f);
    }
    part[ig][c] = acc;
    __syncthreads();
    if (t < 64) {
        float s = part[0][t] + part[1][t] + part[2][t] + part[3][t];
        mout[b * 512 + c0 + t] = s * (1.0f / 4096.0f);
    }
}

// ======================= final 512 -> 2048 =======================
__global__ __launch_bounds__(256) void final_kernel(const float* __restrict__ m,
                                                    const float* __restrict__ w2,
                                                    const float* __restrict__ b2,
                                                    float* __restrict__ out) {
    __shared__ float sm[16 * 512];
    int t = threadIdx.x;
    for (int i = t; i < 16 * 512; i += 256) sm[i] = m[i];
    __syncthreads();

    int warp = t >> 5, lane = t & 31;
    int o = blockIdx.x * 8 + warp;
    float acc[16];
#pragma unroll
    for (int b = 0; b < 16; b++) acc[b] = 0.f;
    const float* wrow = w2 + (size_t)o * 512;
#pragma unroll
    for (int kc = 0; kc < 16; kc++) {
        int k = kc * 32 + lane;
        float wv = wrow[k];
#pragma unroll
        for (int b = 0; b < 16; b++) acc[b] = fmaf(wv, sm[b * 512 + k], acc[b]);
    }
#pragma unroll
    for (int b = 0; b < 16; b++) {
        float v = acc[b];
#pragma unroll
        for (int s = 16; s > 0; s >>= 1) v += __shfl_xor_sync(0xffffffffu, v, s);
        if (lane == 0) out[b * 2048 + o] = v + b2[o];
    }
}

// ======================= launch =======================
extern "C" void kernel_launch(void* const* d_in, const int* in_sizes, int n_in,
                              void* d_out, int out_size) {
    (void)in_sizes; (void)n_in; (void)out_size;
    const float* x   = (const float*)d_in[0];
    const float* e1w = (const float*)d_in[1];
    const float* e1b = (const float*)d_in[2];
    const float* e2w = (const float*)d_in[3];
    const float* e2b = (const float*)d_in[4];
    const float* r1w = (const float*)d_in[5];
    const float* r1b = (const float*)d_in[6];
    const float* r2w = (const float*)d_in[7];
    const float* r2b = (const float*)d_in[8];
    const float* r3w = (const float*)d_in[9];
    const float* r3b = (const float*)d_in[10];
    const float* w1  = (const float*)d_in[11];
    const float* b1  = (const float*)d_in[12];
    const float* w2  = (const float*)d_in[13];
    const float* b2  = (const float*)d_in[14];
    float* out = (float*)d_out;

    __nv_bfloat16 *e128h, *e128l, *e256h, *e256l, *e512h, *e512l, *e1024h, *e1024l;
    __nv_bfloat16 *r1wh, *r1wl, *r2wh, *r2wl, *r3wh, *r3wl, *wabh, *wabl;
    float *AB, *mbuf;
    cudaGetSymbolAddress((void**)&e128h, g_e128h);
    cudaGetSymbolAddress((void**)&e128l, g_e128l);
    cudaGetSymbolAddress((void**)&e256h, g_e256h);
    cudaGetSymbolAddress((void**)&e256l, g_e256l);
    cudaGetSymbolAddress((void**)&e512h, g_e512h);
    cudaGetSymbolAddress((void**)&e512l, g_e512l);
    cudaGetSymbolAddress((void**)&e1024h, g_e1024h);
    cudaGetSymbolAddress((void**)&e1024l, g_e1024l);
    cudaGetSymbolAddress((void**)&r1wh, g_r1wh);
    cudaGetSymbolAddress((void**)&r1wl, g_r1wl);
    cudaGetSymbolAddress((void**)&r2wh, g_r2wh);
    cudaGetSymbolAddress((void**)&r2wl, g_r2wl);
    cudaGetSymbolAddress((void**)&r3wh, g_r3wh);
    cudaGetSymbolAddress((void**)&r3wl, g_r3wl);
    cudaGetSymbolAddress((void**)&wabh, g_wabh);
    cudaGetSymbolAddress((void**)&wabl, g_wabl);
    cudaGetSymbolAddress((void**)&AB, g_AB);
    cudaGetSymbolAddress((void**)&mbuf, g_m);

    cudaFuncSetAttribute(mma_gemm<64, 1>, cudaFuncAttributeMaxDynamicSharedMemorySize, GemmCfg<64>::SMEM);
    cudaFuncSetAttribute(mma_gemm<128, 1>, cudaFuncAttributeMaxDynamicSharedMemorySize, GemmCfg<128>::SMEM);
    cudaFuncSetAttribute(mma_gemm<128, 0>, cudaFuncAttributeMaxDynamicSharedMemorySize, GemmCfg<128>::SMEM);

    // fused prep: all weight splits + embedding (one launch)
    prep_kernel<<<2208, 256>>>(r1w, (__nv_bfloat162*)r1wh, (__nv_bfloat162*)r1wl,
                               r2w, (__nv_bfloat162*)r2wh, (__nv_bfloat162*)r2wl,
                               r3w, (__nv_bfloat162*)r3wh, (__nv_bfloat162*)r3wl,
                               w1, (__nv_bfloat162*)wabh, (__nv_bfloat162*)wabl,
                               x, e1w, e1b, e2w, e2b, e128h, e128l);

    // r1: 128 -> 256 (bias+relu, split out), BM=64 -> 64 CTAs
    mma_gemm<64, 1><<<dim3(4, 16), 128, GemmCfg<64>::SMEM>>>(
        e128h, e128l, r1wh, r1wl, r1b, 128, nullptr, e256h, e256l, 256);
    // r2: 256 -> 512, BM=64 -> 128 CTAs
    mma_gemm<64, 1><<<dim3(8, 16), 128, GemmCfg<64>::SMEM>>>(
        e256h, e256l, r2wh, r2wl, r2b, 256, nullptr, e512h, e512l, 512);
    // r3: 512 -> 1024, BM=128 -> 128 CTAs
    mma_gemm<128, 1><<<dim3(16, 8), 256, GemmCfg<128>::SMEM>>>(
        e512h, e512l, r3wh, r3wl, r3b, 512, nullptr, e1024h, e1024l, 1024);
    // A|B fused: 1024 -> 1024 (raw fp32 out), BM=128 -> 128 CTAs
    mma_gemm<128, 0><<<dim3(16, 8), 256, GemmCfg<128>::SMEM>>>(
        e1024h, e1024l, wabh, wabl, nullptr, 1024, AB, nullptr, nullptr, 1024);

    // pairwise mean -> m[16][512]
    pairwise_kernel<<<dim3(8, 16), 256>>>(AB, b1, mbuf);

    // final 512 -> 2048
    final_kernel<<<2048 / 8, 256>>>(mbuf, w2, b2, out);
}

// round 8
// speedup vs baseline: 1.4327x; 1.0315x over previous
#include <cuda_runtime.h>
#include <cuda_bf16.h>
#include <stdint.h>

#define DINLINE __device__ __forceinline__

DINLINE uint32_t smem_u32(const void* p) {
    uint32_t a;
    asm("{ .reg .u64 t; cvta.to.shared.u64 t, %1; cvt.u32.u64 %0, t; }" : "=r"(a) : "l"(p));
    return a;
}

DINLINE void ldsm_x4(uint32_t addr, uint32_t* r) {
    asm volatile("ldmatrix.sync.aligned.m8n8.x4.shared.b16 {%0,%1,%2,%3}, [%4];"
                 : "=r"(r[0]), "=r"(r[1]), "=r"(r[2]), "=r"(r[3]) : "r"(addr));
}

DINLINE void mma16816(float* d, const uint32_t* a, const uint32_t* b) {
    asm volatile("mma.sync.aligned.m16n8k16.row.col.f32.bf16.bf16.f32 "
                 "{%0,%1,%2,%3}, {%4,%5,%6,%7}, {%8,%9}, {%0,%1,%2,%3};"
                 : "+f"(d[0]), "+f"(d[1]), "+f"(d[2]), "+f"(d[3])
                 : "r"(a[0]), "r"(a[1]), "r"(a[2]), "r"(a[3]), "r"(b[0]), "r"(b[1]));
}

DINLINE void cp16(uint32_t saddr, const void* g) {
    asm volatile("cp.async.cg.shared.global [%0], [%1], 16;" :: "r"(saddr), "l"(g));
}
DINLINE void cp_commit() { asm volatile("cp.async.commit_group;" ::: "memory"); }
DINLINE void cp_wait0() { asm volatile("cp.async.wait_group 0;" ::: "memory"); }
DINLINE void cp_wait1() { asm volatile("cp.async.wait_group 1;" ::: "memory"); }
DINLINE void cp_wait2() { asm volatile("cp.async.wait_group 2;" ::: "memory"); }

DINLINE void split2(float a, float b, __nv_bfloat162& h, __nv_bfloat162& l) {
    h = __floats2bfloat162_rn(a, b);
    l = __floats2bfloat162_rn(a - __low2float(h), b - __high2float(h));
}

// ======================= scratch (no allocs) =======================
__device__ __align__(16) __nv_bfloat16 g_e128h[1024 * 128];
__device__ __align__(16) __nv_bfloat16 g_e128l[1024 * 128];
__device__ __align__(16) __nv_bfloat16 g_e256h[1024 * 256];
__device__ __align__(16) __nv_bfloat16 g_e256l[1024 * 256];
__device__ __align__(16) __nv_bfloat16 g_e512h[1024 * 512];
__device__ __align__(16) __nv_bfloat16 g_e512l[1024 * 512];
__device__ __align__(16) __nv_bfloat16 g_e1024h[1024 * 1024];
__device__ __align__(16) __nv_bfloat16 g_e1024l[1024 * 1024];
__device__ __align__(16) __nv_bfloat16 g_r1wh[256 * 128];
__device__ __align__(16) __nv_bfloat16 g_r1wl[256 * 128];
__device__ __align__(16) __nv_bfloat16 g_r2wh[512 * 256];
__device__ __align__(16) __nv_bfloat16 g_r2wl[512 * 256];
__device__ __align__(16) __nv_bfloat16 g_r3wh[1024 * 512];
__device__ __align__(16) __nv_bfloat16 g_r3wl[1024 * 512];
__device__ __align__(16) __nv_bfloat16 g_wabh[1024 * 1024];
__device__ __align__(16) __nv_bfloat16 g_wabl[1024 * 1024];
__device__ __align__(16) float g_AB[1024 * 1024];   // cols [0,512)=A, [512,1024)=B
__device__ __align__(16) float g_m[16 * 512];

// ======================= fused prep: all weight splits + embedding =======================
DINLINE void split_store4(const float4* __restrict__ src, __nv_bfloat162* __restrict__ h,
                          __nv_bfloat162* __restrict__ l, int i) {
    float4 v = src[i];
    __nv_bfloat162 h0, l0, h1, l1;
    split2(v.x, v.y, h0, l0);
    split2(v.z, v.w, h1, l1);
    h[2 * i] = h0; h[2 * i + 1] = h1;
    l[2 * i] = l0; l[2 * i + 1] = l1;
}

// blocks: [0,32) r1w, [32,160) r2w, [160,672) r3w, [672,1696) w1 gather, [1696,2208) embed
__global__ __launch_bounds__(256) void prep_kernel(
    const float* __restrict__ r1w, __nv_bfloat162* __restrict__ r1h, __nv_bfloat162* __restrict__ r1l,
    const float* __restrict__ r2w, __nv_bfloat162* __restrict__ r2h, __nv_bfloat162* __restrict__ r2l,
    const float* __restrict__ r3w, __nv_bfloat162* __restrict__ r3h, __nv_bfloat162* __restrict__ r3l,
    const float* __restrict__ w1, __nv_bfloat162* __restrict__ wabh, __nv_bfloat162* __restrict__ wabl,
    const float* __restrict__ x,
    const float* __restrict__ e1w, const float* __restrict__ e1b,
    const float* __restrict__ e2w, const float* __restrict__ e2b,
    __nv_bfloat16* __restrict__ oh, __nv_bfloat16* __restrict__ ol) {
    int b = blockIdx.x, tid = threadIdx.x;
    if (b < 32) {
        split_store4((const float4*)r1w, r1h, r1l, b * 256 + tid);
    } else if (b < 160) {
        split_store4((const float4*)r2w, r2h, r2l, (b - 32) * 256 + tid);
    } else if (b < 672) {
        split_store4((const float4*)r3w, r3h, r3l, (b - 160) * 256 + tid);
    } else if (b < 1696) {
        int i = (b - 672) * 256 + tid;      // over 1024*256 float4 groups
        int n = i >> 8, kq = i & 255;
        const float* src = (n < 512) ? (w1 + (size_t)n * 2048 + kq * 4)
                                     : (w1 + (size_t)(n - 512) * 2048 + 1024 + kq * 4);
        float4 v = *(const float4*)src;
        __nv_bfloat162 h0, l0, h1, l1;
        split2(v.x, v.y, h0, l0);
        split2(v.z, v.w, h1, l1);
        size_t o = (size_t)n * 512 + kq * 2;
        wabh[o] = h0; wabh[o + 1] = h1;
        wabl[o] = l0; wabl[o + 1] = l1;
    } else {
        __shared__ float xr[2][16];
        int rb = tid >> 7;
        int t = tid & 127;
        int row = (b - 1696) * 2 + rb;
        if (t < 16) xr[rb][t] = x[row * 16 + t];
        __syncthreads();
        float s1 = e1b[t];
#pragma unroll
        for (int c = 0; c < 3; c++) s1 = fmaf(xr[rb][c], e1w[t * 3 + c], s1);
        float s2 = e2b[t];
#pragma unroll
        for (int c = 0; c < 13; c++) s2 = fmaf(xr[rb][3 + c], e2w[t * 13 + c], s2);
        float v = fmaxf(s1, 0.f) + fmaxf(s2, 0.f);
        __nv_bfloat16 h = __float2bfloat16(v);
        oh[row * 128 + t] = h;
        ol[row * 128 + t] = __float2bfloat16(v - __bfloat162float(h));
    }
}

// ======================= warp-mma split-bf16 GEMM, 4-stage cp.async (2-3 groups in flight) ==========
// C[m][n] = sum_k (Ah+Al)[m][k] * (Wh+Wl)[n][k], 3-term split, fp32 accumulate.
// CTA tile BM x 64, BM*2 threads (BM/32 x 2 warps), warp tile 32x32. K mult of 64.
// OUTM==0: raw fp32 out. OUTM==1: bias+relu, split bf16 out.
static constexpr int GSTRIDE = 144;   // 64 bf16 = 128B + 16B pad
static constexpr int NSTAGE = 4;

template <int BM> struct GemmCfg {
    static constexpr int T = BM * 2;
    static constexpr int OFF_AL = BM * GSTRIDE;
    static constexpr int OFF_WH = 2 * BM * GSTRIDE;
    static constexpr int OFF_WL = OFF_WH + 64 * GSTRIDE;
    static constexpr int STAGE = OFF_WL + 64 * GSTRIDE;
    static constexpr int SMEM = NSTAGE * STAGE;
};

template <int BM, int OUTM>
__global__ __launch_bounds__(BM * 2) void mma_gemm(
    const __nv_bfloat16* __restrict__ Ah, const __nv_bfloat16* __restrict__ Al,
    const __nv_bfloat16* __restrict__ Wh, const __nv_bfloat16* __restrict__ Wl,
    const float* __restrict__ bias, int K,
    float* __restrict__ outF, __nv_bfloat16* __restrict__ outH,
    __nv_bfloat16* __restrict__ outL, int ldo) {
    using C = GemmCfg<BM>;
    extern __shared__ char smc[];
    uint32_t sbase = smem_u32(smc);

    int tid = threadIdx.x, lane = tid & 31, wid = tid >> 5;
    int mw = wid >> 1, nw = wid & 1;
    int m0 = blockIdx.y * BM, n0 = blockIdx.x * 64;

    float acc[2][4][4] = {};

    uint32_t aoff = (lane & 15) * GSTRIDE + ((lane >> 4) << 4);
    uint32_t boff = ((((lane >> 4) << 3) + (lane & 7)) * GSTRIDE) + (((lane >> 3) & 1) << 4);
    uint32_t aBase0 = sbase + mw * 32 * GSTRIDE + aoff;
    uint32_t bBase0 = sbase + C::OFF_WH + nw * 32 * GSTRIDE + boff;

    constexpr int RPI = C::T / 8;
    int lrow = tid >> 3, lu = tid & 7;
    uint32_t sAh = sbase, sAl = sbase + C::OFF_AL, sWh = sbase + C::OFF_WH, sWl = sbase + C::OFF_WL;

    int nc = K >> 6;

    auto load_stage = [&](int c) {     // stage c -> slot c % NSTAGE
        int k0 = c << 6;
        uint32_t so = (uint32_t)(c & (NSTAGE - 1)) * C::STAGE;
#pragma unroll
        for (int q = 0; q < BM / RPI; ++q) {
            int row = lrow + q * RPI;
            size_t go = (size_t)(m0 + row) * K + k0 + lu * 8;
            uint32_t sro = row * GSTRIDE + lu * 16 + so;
            cp16(sAh + sro, Ah + go);
            cp16(sAl + sro, Al + go);
        }
#pragma unroll
        for (int q = 0; q < 64 / RPI; ++q) {
            int row = lrow + q * RPI;
            size_t go = (size_t)(n0 + row) * K + k0 + lu * 8;
            uint32_t sro = row * GSTRIDE + lu * 16 + so;
            cp16(sWh + sro, Wh + go);
            cp16(sWl + sro, Wl + go);
        }
        cp_commit();
    };

    // prologue: keep up to 3 stages in flight
    int issued = (nc < 3) ? nc : 3;
    for (int c = 0; c < issued; ++c) load_stage(c);

    for (int c = 0; c < nc; ++c) {
        int w = issued - c - 1;                 // groups allowed to stay in flight
        if (w <= 0) cp_wait0();
        else if (w == 1) cp_wait1();
        else cp_wait2();
        __syncthreads();                        // all threads' stage-c data visible;
                                                // all warps done computing stage c-1
        if (issued < nc) { load_stage(issued); ++issued; }

        uint32_t so = (uint32_t)(c & (NSTAGE - 1)) * C::STAGE;
        uint32_t aBase = aBase0 + so, bBase = bBase0 + so;
#pragma unroll
        for (int kk = 0; kk < 4; ++kk) {
            uint32_t ah[2][4], al[2][4], bh[4][2], bl[4][2];
#pragma unroll
            for (int mi = 0; mi < 2; ++mi) {
                ldsm_x4(aBase + mi * (16 * GSTRIDE) + kk * 32, ah[mi]);
                ldsm_x4(aBase + C::OFF_AL + mi * (16 * GSTRIDE) + kk * 32, al[mi]);
            }
#pragma unroll
            for (int p = 0; p < 2; ++p) {
                uint32_t r4[4];
                ldsm_x4(bBase + p * (16 * GSTRIDE) + kk * 32, r4);
                bh[2 * p][0] = r4[0]; bh[2 * p][1] = r4[1];
                bh[2 * p + 1][0] = r4[2]; bh[2 * p + 1][1] = r4[3];
                ldsm_x4(bBase + (C::OFF_WL - C::OFF_WH) + p * (16 * GSTRIDE) + kk * 32, r4);
                bl[2 * p][0] = r4[0]; bl[2 * p][1] = r4[1];
                bl[2 * p + 1][0] = r4[2]; bl[2 * p + 1][1] = r4[3];
            }
#pragma unroll
            for (int mi = 0; mi < 2; ++mi)
#pragma unroll
                for (int ni = 0; ni < 4; ++ni) {
                    mma16816(acc[mi][ni], ah[mi], bh[ni]);
                    mma16816(acc[mi][ni], ah[mi], bl[ni]);
                    mma16816(acc[mi][ni], al[mi], bh[ni]);
                }
        }
    }

    int r = lane >> 2, c2 = (lane & 3) * 2;
    int warpM = m0 + mw * 32, warpN = n0 + nw * 32;
#pragma unroll
    for (int mi = 0; mi < 2; ++mi)
#pragma unroll
        for (int ni = 0; ni < 4; ++ni) {
            int n = warpN + ni * 8 + c2;
#pragma unroll
            for (int h = 0; h < 2; ++h) {
                int m = warpM + mi * 16 + r + h * 8;
                float v0 = acc[mi][ni][h * 2 + 0];
                float v1 = acc[mi][ni][h * 2 + 1];
                if (OUTM == 1) {
                    float2 bb = *(const float2*)(bias + n);
                    v0 = fmaxf(v0 + bb.x, 0.f);
                    v1 = fmaxf(v1 + bb.y, 0.f);
                    __nv_bfloat162 hh, ll;
                    split2(v0, v1, hh, ll);
                    *(__nv_bfloat162*)(outH + (size_t)m * ldo + n) = hh;
                    *(__nv_bfloat162*)(outL + (size_t)m * ldo + n) = ll;
                } else {
                    *(float2*)(outF + (size_t)m * ldo + n) = make_float2(v0, v1);
                }
            }
        }
}

// ======================= pairwise relu outer-sum mean =======================
__global__ __launch_bounds__(256) void pairwise_kernel(const float* __restrict__ AB,
                                                       const float* __restrict__ b1,
                                                       float* __restrict__ mout) {
    __shared__ float As[64][64];
    __shared__ float Bs[64][64];
    __shared__ float part[4][64];
    int t = threadIdx.x;
    int chunk = blockIdx.x;
    int b = blockIdx.y;
    int c0 = chunk * 64;
    const float* base = AB + (size_t)b * 64 * 1024;

#pragma unroll
    for (int q = 0; q < 4; q++) {
        int idx = t + q * 256;
        int row = idx >> 4;
        int seg = idx & 15;
        float4 va = *(const float4*)(base + row * 1024 + c0 + seg * 4);
        float4 vb = *(const float4*)(base + row * 1024 + 512 + c0 + seg * 4);
        *(float4*)&As[row][seg * 4] = va;
        *(float4*)&Bs[row][seg * 4] = vb;
    }
    __syncthreads();

    int c = t & 63;
    int ig = t >> 6;
    float bias = b1[c0 + c];
    float acc = 0.f;
    for (int i = ig * 16; i < ig * 16 + 16; i++) {
        float bb = Bs[i][c] + bias;
#pragma unroll
        for (int j = 0; j < 64; j++)
            acc += fmaxf(As[j][c] + bb, 0.f);
    }
    part[ig][c] = acc;
    __syncthreads();
    if (t < 64) {
        float s = part[0][t] + part[1][t] + part[2][t] + part[3][t];
        mout[b * 512 + c0 + t] = s * (1.0f / 4096.0f);
    }
}

// ======================= final 512 -> 2048 =======================
__global__ __launch_bounds__(256) void final_kernel(const float* __restrict__ m,
                                                    const float* __restrict__ w2,
                                                    const float* __restrict__ b2,
                                                    float* __restrict__ out) {
    __shared__ float sm[16 * 512];
    int t = threadIdx.x;
    for (int i = t; i < 16 * 512; i += 256) sm[i] = m[i];
    __syncthreads();

    int warp = t >> 5, lane = t & 31;
    int o = blockIdx.x * 8 + warp;
    float acc[16];
#pragma unroll
    for (int b = 0; b < 16; b++) acc[b] = 0.f;
    const float* wrow = w2 + (size_t)o * 512;
#pragma unroll
    for (int kc = 0; kc < 16; kc++) {
        int k = kc * 32 + lane;
        float wv = wrow[k];
#pragma unroll
        for (int b = 0; b < 16; b++) acc[b] = fmaf(wv, sm[b * 512 + k], acc[b]);
    }
#pragma unroll
    for (int b = 0; b < 16; b++) {
        float v = acc[b];
#pragma unroll
        for (int s = 16; s > 0; s >>= 1) v += __shfl_xor_sync(0xffffffffu, v, s);
        if (lane == 0) out[b * 2048 + o] = v + b2[o];
    }
}

// ======================= launch =======================
extern "C" void kernel_launch(void* const* d_in, const int* in_sizes, int n_in,
                              void* d_out, int out_size) {
    (void)in_sizes; (void)n_in; (void)out_size;
    const float* x   = (const float*)d_in[0];
    const float* e1w = (const float*)d_in[1];
    const float* e1b = (const float*)d_in[2];
    const float* e2w = (const float*)d_in[3];
    const float* e2b = (const float*)d_in[4];
    const float* r1w = (const float*)d_in[5];
    const float* r1b = (const float*)d_in[6];
    const float* r2w = (const float*)d_in[7];
    const float* r2b = (const float*)d_in[8];
    const float* r3w = (const float*)d_in[9];
    const float* r3b = (const float*)d_in[10];
    const float* w1  = (const float*)d_in[11];
    const float* b1  = (const float*)d_in[12];
    const float* w2  = (const float*)d_in[13];
    const float* b2  = (const float*)d_in[14];
    float* out = (float*)d_out;

    __nv_bfloat16 *e128h, *e128l, *e256h, *e256l, *e512h, *e512l, *e1024h, *e1024l;
    __nv_bfloat16 *r1wh, *r1wl, *r2wh, *r2wl, *r3wh, *r3wl, *wabh, *wabl;
    float *AB, *mbuf;
    cudaGetSymbolAddress((void**)&e128h, g_e128h);
    cudaGetSymbolAddress((void**)&e128l, g_e128l);
    cudaGetSymbolAddress((void**)&e256h, g_e256h);
    cudaGetSymbolAddress((void**)&e256l, g_e256l);
    cudaGetSymbolAddress((void**)&e512h, g_e512h);
    cudaGetSymbolAddress((void**)&e512l, g_e512l);
    cudaGetSymbolAddress((void**)&e1024h, g_e1024h);
    cudaGetSymbolAddress((void**)&e1024l, g_e1024l);
    cudaGetSymbolAddress((void**)&r1wh, g_r1wh);
    cudaGetSymbolAddress((void**)&r1wl, g_r1wl);
    cudaGetSymbolAddress((void**)&r2wh, g_r2wh);
    cudaGetSymbolAddress((void**)&r2wl, g_r2wl);
    cudaGetSymbolAddress((void**)&r3wh, g_r3wh);
    cudaGetSymbolAddress((void**)&r3wl, g_r3wl);
    cudaGetSymbolAddress((void**)&wabh, g_wabh);
    cudaGetSymbolAddress((void**)&wabl, g_wabl);
    cudaGetSymbolAddress((void**)&AB, g_AB);
    cudaGetSymbolAddress((void**)&mbuf, g_m);

    cudaFuncSetAttribute(mma_gemm<64, 1>, cudaFuncAttributeMaxDynamicSharedMemorySize, GemmCfg<64>::SMEM);
    cudaFuncSetAttribute(mma_gemm<128, 1>, cudaFuncAttributeMaxDynamicSharedMemorySize, GemmCfg<128>::SMEM);
    cudaFuncSetAttribute(mma_gemm<128, 0>, cudaFuncAttributeMaxDynamicSharedMemorySize, GemmCfg<128>::SMEM);

    // fused prep: all weight splits + embedding (one launch)
    prep_kernel<<<2208, 256>>>(r1w, (__nv_bfloat162*)r1wh, (__nv_bfloat162*)r1wl,
                               r2w, (__nv_bfloat162*)r2wh, (__nv_bfloat162*)r2wl,
                               r3w, (__nv_bfloat162*)r3wh, (__nv_bfloat162*)r3wl,
                               w1, (__nv_bfloat162*)wabh, (__nv_bfloat162*)wabl,
                               x, e1w, e1b, e2w, e2b, e128h, e128l);

    // r1: 128 -> 256 (bias+relu, split out), BM=64 -> 64 CTAs
    mma_gemm<64, 1><<<dim3(4, 16), 128, GemmCfg<64>::SMEM>>>(
        e128h, e128l, r1wh, r1wl, r1b, 128, nullptr, e256h, e256l, 256);
    // r2: 256 -> 512, BM=64 -> 128 CTAs
    mma_gemm<64, 1><<<dim3(8, 16), 128, GemmCfg<64>::SMEM>>>(
        e256h, e256l, r2wh, r2wl, r2b, 256, nullptr, e512h, e512l, 512);
    // r3: 512 -> 1024, BM=128 -> 128 CTAs
    mma_gemm<128, 1><<<dim3(16, 8), 256, GemmCfg<128>::SMEM>>>(
        e512h, e512l, r3wh, r3wl, r3b, 512, nullptr, e1024h, e1024l, 1024);
    // A|B fused: 1024 -> 1024 (raw fp32 out), BM=128 -> 128 CTAs
    mma_gemm<128, 0><<<dim3(16, 8), 256, GemmCfg<128>::SMEM>>>(
        e1024h, e1024l, wabh, wabl, nullptr, 1024, AB, nullptr, nullptr, 1024);

    // pairwise mean -> m[16][512]
    pairwise_kernel<<<dim3(8, 16), 256>>>(AB, b1, mbuf);

    // final 512 -> 2048
    final_kernel<<<2048 / 8, 256>>>(mbuf, w2, b2, out);
}